// round 10
// baseline (speedup 1.0000x reference)
#include <cuda_runtime.h>

#define TPB 256
#define PAD_A 68   // staging/A pad (float4-aligned, phase-conflict-free)
#define PAD_C 65   // C pad (odd: conflict-free row+col scalar access)
#define PAD_G 67
// buf (256*PAD_A overlay for A and C) + sB + sG + small vectors
#define SMEM_FLOATS (256*PAD_A + 64*PAD_A + 64*PAD_G + 64*5 + 128)
#define SMEM_BYTES (SMEM_FLOATS * 4)

__device__ __forceinline__ unsigned long long pk2(float x, float y) {
    unsigned long long r;
    asm("mov.b64 %0, {%1, %2};" : "=l"(r) : "f"(x), "f"(y));
    return r;
}
__device__ __forceinline__ void upk2(unsigned long long v, float &x, float &y) {
    asm("mov.b64 {%0, %1}, %2;" : "=f"(x), "=f"(y) : "l"(v));
}
__device__ __forceinline__ void fma2(unsigned long long &d, unsigned long long a, unsigned long long b) {
    asm("fma.rn.f32x2 %0, %1, %2, %0;" : "+l"(d) : "l"(a), "l"(b));
}

__global__ void __launch_bounds__(TPB, 2) conn_kernel(
    const float* __restrict__ x, const float* __restrict__ v,
    const float* __restrict__ W1, const float* __restrict__ b1,
    const float* __restrict__ W2, const float* __restrict__ b2g,
    const float* __restrict__ W3, float* __restrict__ out)
{
    const int n = blockIdx.x;
    const int t = threadIdx.x;

    extern __shared__ float smem[];
    float* buf = smem;                    // overlay: sA [256][PAD_A] / sC [256][PAD_C]
    float* sB  = buf + 256 * PAD_A;       // [64][PAD_A]  B[m][l] = s[m]*W1[m][l]
    float* sG  = sB  + 64 * PAD_A;        // [64][PAD_G]  g augmented (col 64 = rhs)
    float* sh  = sG  + 64 * PAD_G;        // h
    float* sv  = sh  + 64;                // v row
    float* sx  = sv  + 64;                // x row
    float* ssc = sx  + 64;                // s = 1 - h^2
    float* sf  = ssc + 64;                // GJ factors
    float* sz  = sf  + 64;                // [128] concat(v, dv)

    // ---- load x, v ----
    if (t < 64) { sx[t] = x[n*64 + t]; sv[t] = v[n*64 + t]; }
    __syncthreads();

    // ---- h = tanh(W1 x + b1), s = 1 - h^2 ----
    {
        const int m = t >> 2, q = t & 3;
        const float4* w1r = (const float4*)(W1 + m*64 + q*16);
        float p = 0.f;
        #pragma unroll
        for (int k = 0; k < 4; k++) {
            float4 wv = w1r[k];
            const float* xs = sx + q*16 + k*4;
            p += wv.x*xs[0] + wv.y*xs[1] + wv.z*xs[2] + wv.w*xs[3];
        }
        p += __shfl_xor_sync(0xffffffffu, p, 1);
        p += __shfl_xor_sync(0xffffffffu, p, 2);
        if (q == 0) {
            float hh = tanhf(p + b1[m]);
            sh[m]  = hh;
            ssc[m] = 1.f - hh*hh;
        }
    }
    __syncthreads();

    // ---- sB[m][l] = s[m] * W1[m][l] ----
    {
        const int m = t >> 2, q = t & 3;
        const float sm_ = ssc[m];
        const float4* w1r = (const float4*)(W1 + m*64 + q*16);
        float4* dst = (float4*)(sB + m*PAD_A + q*16);
        #pragma unroll
        for (int k = 0; k < 4; k++) {
            float4 wv = w1r[k];
            wv.x *= sm_; wv.y *= sm_; wv.z *= sm_; wv.w *= sm_;
            dst[k] = wv;
        }
    }
    // (first stage __syncthreads orders sB before GEMM reads)

    float wacc[16];
    #pragma unroll
    for (int k = 0; k < 16; k++) wacc[k] = 0.f;

    const int tx = t & 7;       // GEMM col group (0..7): cols {4tx..} and {32+4tx..}
    const int ty = t >> 3;      // GEMM row base (0..31): rows ty + 32a
    const int rr = t & 63;      // consume/stage row index
    const int pp = t >> 6;      // consume l-part / stage block index

    const float* bcol0 = sB + 4*tx;        // B column base (low half)
    const float* arow0 = buf + ty*PAD_A;   // A row base

    // ============ group loop: 4 bb blocks per iteration ============
    for (int g = 0; g < 16; ++g) {
        const int bb0 = g * 4;

        // ---- stage 4 Wsym blocks into buf-as-A; fuse g-column dot with h ----
        {
            const int u = pp, r = rr;
            const int bb = bb0 + u;
            const float4* p1 = (const float4*)(W2 + (bb*64 + r)*64);
            const float4* p2 = (const float4*)(W2 + (r*64 + bb)*64);
            float* dst = buf + (u*64 + r)*PAD_A;
            float gp = 0.f;
            #pragma unroll
            for (int k = 0; k < 16; ++k) {
                float4 a1 = p1[k];
                float4 a2 = p2[k];
                a1.x += a2.x; a1.y += a2.y; a1.z += a2.z; a1.w += a2.w;
                *(float4*)(dst + 4*k) = a1;
                const float* hp = sh + 4*k;
                gp += a1.x*hp[0] + a1.y*hp[1] + a1.z*hp[2] + a1.w*hp[3];
            }
            sG[r*PAD_G + bb] = gp + b2g[bb*64 + r] + b2g[r*64 + bb];
        }
        __syncthreads();

        // ---- GEMM: Cstack(256x64) = Astack(256x64) @ B(64x64), 8x8 tile/thread ----
        unsigned long long acc[8][4];
        #pragma unroll
        for (int a = 0; a < 8; ++a) {
            acc[a][0] = 0ull; acc[a][1] = 0ull; acc[a][2] = 0ull; acc[a][3] = 0ull;
        }

        #pragma unroll 1
        for (int m4 = 0; m4 < 64; m4 += 4) {
            // B fragments loaded DIRECTLY as f32x2 pairs (no pack movs, no
            // float4 temporaries): same 16 bytes, reinterpret as ulonglong2.
            unsigned long long bfr[4][4];
            #pragma unroll
            for (int mm = 0; mm < 4; ++mm) {
                const float* brow = bcol0 + (m4 + mm)*PAD_A;
                const ulonglong2 b0 = *(const ulonglong2*)(brow);
                const ulonglong2 b1 = *(const ulonglong2*)(brow + 32);
                bfr[mm][0] = b0.x; bfr[mm][1] = b0.y;
                bfr[mm][2] = b1.x; bfr[mm][3] = b1.y;
            }
            #pragma unroll
            for (int a = 0; a < 8; ++a) {
                const float4 av = *(const float4*)(arow0 + (32*a)*PAD_A + m4);
                #pragma unroll
                for (int mm = 0; mm < 4; ++mm) {
                    const float s = (mm == 0) ? av.x : (mm == 1) ? av.y
                                  : (mm == 2) ? av.z : av.w;
                    const unsigned long long aa = pk2(s, s);
                    fma2(acc[a][0], aa, bfr[mm][0]);
                    fma2(acc[a][1], aa, bfr[mm][1]);
                    fma2(acc[a][2], aa, bfr[mm][2]);
                    fma2(acc[a][3], aa, bfr[mm][3]);
                }
            }
        }
        __syncthreads();   // everyone done reading buf-as-A

        // ---- store C into buf-as-C (pad 65, scalar stores: phase-conflict-free) ----
        #pragma unroll
        for (int a = 0; a < 8; ++a) {
            float* crow = buf + (ty + 32*a)*PAD_C;
            float f0, f1;
            upk2(acc[a][0], f0, f1); crow[4*tx]      = f0; crow[4*tx + 1]      = f1;
            upk2(acc[a][1], f0, f1); crow[4*tx + 2]  = f0; crow[4*tx + 3]      = f1;
            upk2(acc[a][2], f0, f1); crow[32 + 4*tx] = f0; crow[32 + 4*tx + 1] = f1;
            upk2(acc[a][3], f0, f1); crow[32 + 4*tx + 2] = f0; crow[32 + 4*tx + 3] = f1;
        }
        __syncthreads();

        // ---- consume: w[l] += v_bb v_j C[j][l]^2 C[l][j] for the 4 blocks ----
        #pragma unroll
        for (int u = 0; u < 4; ++u) {
            const float coef = sv[bb0 + u] * sv[rr];
            const float* crow  = buf + (u*64 + rr)*PAD_C;
            const float* cbase = buf + (u*64)*PAD_C + rr;
            #pragma unroll
            for (int k = 0; k < 16; ++k) {
                const int l = pp*16 + k;
                const float c  = crow[l];
                const float ct = cbase[l*PAD_C];
                wacc[k] += coef * c * c * ct;
            }
        }
        __syncthreads();   // before next stage overwrites buf
    }

    // ---- reduce wacc over j into rhs column of sG (reuse buf as scratch) ----
    #pragma unroll
    for (int k = 0; k < 16; k++) buf[rr*PAD_C + pp*16 + k] = wacc[k];
    __syncthreads();
    if (t < 64) {
        float s = 0.f;
        for (int r = 0; r < 64; r++) s += buf[r*PAD_C + t];
        sG[t*PAD_G + 64] = s;
    }
    __syncthreads();

    // ---- Gauss-Jordan solve g y = w  (g SPD-ish, no pivoting) ----
    {
        const int r    = t & 63;
        const int part = t >> 6;
        const int cbeg = part * 16;
        for (int p = 0; p < 64; p++) {
            if (t < 64) {
                const float piv = sG[p*PAD_G + p];
                sf[t] = (t == p) ? 0.f : sG[t*PAD_G + p] / piv;
            }
            __syncthreads();
            if (r != p) {
                const float fr = sf[r];
                const float* prow = sG + p*PAD_G;
                float* rrow = sG + r*PAD_G;
                #pragma unroll
                for (int c = 0; c < 16; c++)
                    rrow[cbeg + c] -= fr * prow[cbeg + c];
                if (part == 3)
                    rrow[64] -= fr * prow[64];
            }
            __syncthreads();
        }
    }

    // ---- dv = 0.5 * y ; z = concat(v, dv) ----
    if (t < 64) {
        const float y = sG[t*PAD_G + 64] / sG[t*PAD_G + t];
        sz[t]      = sv[t];
        sz[64 + t] = 0.5f * y;
    }
    __syncthreads();

    // ---- out[n,k] = sum_c z[c] * W3[k, c] ----
    {
        const int k = t >> 2, q = t & 3;
        const float4* w3r = (const float4*)(W3 + k*128 + q*32);
        float p = 0.f;
        #pragma unroll
        for (int j = 0; j < 8; j++) {
            float4 wv = w3r[j];
            const float* zz = sz + q*32 + j*4;
            p += wv.x*zz[0] + wv.y*zz[1] + wv.z*zz[2] + wv.w*zz[3];
        }
        p += __shfl_xor_sync(0xffffffffu, p, 1);
        p += __shfl_xor_sync(0xffffffffu, p, 2);
        if (q == 0) out[n*64 + k] = p;
    }
}

extern "C" void kernel_launch(void* const* d_in, const int* in_sizes, int n_in,
                              void* d_out, int out_size)
{
    // inputs: 0:t (unused), 1:x (256*64), 2:v, 3:W1, 4:b1, 5:W2 (4096*64),
    //         6:b2 (4096), 7:W3 (64*128); output: (256,64) fp32
    const float* x  = (const float*)d_in[1];
    const float* v  = (const float*)d_in[2];
    const float* W1 = (const float*)d_in[3];
    const float* b1 = (const float*)d_in[4];
    const float* W2 = (const float*)d_in[5];
    const float* b2 = (const float*)d_in[6];
    const float* W3 = (const float*)d_in[7];

    cudaFuncSetAttribute(conn_kernel,
                         cudaFuncAttributeMaxDynamicSharedMemorySize, SMEM_BYTES);
    conn_kernel<<<256, TPB, SMEM_BYTES>>>(x, v, W1, b1, W2, b2, W3, (float*)d_out);
}

// round 12
// speedup vs baseline: 1.0468x; 1.0468x over previous
#include <cuda_runtime.h>

#define TPB 256
#define PAD_A 68   // staging/A pad (float4-aligned, phase-conflict-free)
#define PAD_C 65   // C pad (odd: conflict-free row+col scalar access)
#define PAD_G 67
// buf (256*PAD_A overlay for A and C) + sB + sG + small vectors
#define SMEM_FLOATS (256*PAD_A + 64*PAD_A + 64*PAD_G + 64*5 + 128)
#define SMEM_BYTES (SMEM_FLOATS * 4)

__device__ __forceinline__ unsigned long long pk2(float x, float y) {
    unsigned long long r;
    asm("mov.b64 %0, {%1, %2};" : "=l"(r) : "f"(x), "f"(y));
    return r;
}
__device__ __forceinline__ void upk2(unsigned long long v, float &x, float &y) {
    asm("mov.b64 {%0, %1}, %2;" : "=f"(x), "=f"(y) : "l"(v));
}
__device__ __forceinline__ void fma2(unsigned long long &d, unsigned long long a, unsigned long long b) {
    asm("fma.rn.f32x2 %0, %1, %2, %0;" : "+l"(d) : "l"(a), "l"(b));
}

__global__ void __launch_bounds__(TPB, 2) conn_kernel(
    const float* __restrict__ x, const float* __restrict__ v,
    const float* __restrict__ W1, const float* __restrict__ b1,
    const float* __restrict__ W2, const float* __restrict__ b2g,
    const float* __restrict__ W3, float* __restrict__ out)
{
    const int n = blockIdx.x;
    const int t = threadIdx.x;

    extern __shared__ float smem[];
    float* buf = smem;                    // overlay: sA [256][PAD_A] / sC [256][PAD_C]
    float* sB  = buf + 256 * PAD_A;       // [64][PAD_A]  B[m][l] = s[m]*W1[m][l]
    float* sG  = sB  + 64 * PAD_A;        // [64][PAD_G]  g augmented (col 64 = rhs)
    float* sh  = sG  + 64 * PAD_G;        // h
    float* sv  = sh  + 64;                // v row
    float* sx  = sv  + 64;                // x row
    float* ssc = sx  + 64;                // s = 1 - h^2
    float* sf  = ssc + 64;                // GJ factors
    float* sz  = sf  + 64;                // [128] concat(v, dv)

    // ---- load x, v ----
    if (t < 64) { sx[t] = x[n*64 + t]; sv[t] = v[n*64 + t]; }
    __syncthreads();

    // ---- h = tanh(W1 x + b1), s = 1 - h^2 ----
    {
        const int m = t >> 2, q = t & 3;
        const float4* w1r = (const float4*)(W1 + m*64 + q*16);
        float p = 0.f;
        #pragma unroll
        for (int k = 0; k < 4; k++) {
            float4 wv = w1r[k];
            const float* xs = sx + q*16 + k*4;
            p += wv.x*xs[0] + wv.y*xs[1] + wv.z*xs[2] + wv.w*xs[3];
        }
        p += __shfl_xor_sync(0xffffffffu, p, 1);
        p += __shfl_xor_sync(0xffffffffu, p, 2);
        if (q == 0) {
            float hh = tanhf(p + b1[m]);
            sh[m]  = hh;
            ssc[m] = 1.f - hh*hh;
        }
    }
    __syncthreads();

    // ---- sB[m][l] = s[m] * W1[m][l] ----
    {
        const int m = t >> 2, q = t & 3;
        const float sm_ = ssc[m];
        const float4* w1r = (const float4*)(W1 + m*64 + q*16);
        float4* dst = (float4*)(sB + m*PAD_A + q*16);
        #pragma unroll
        for (int k = 0; k < 4; k++) {
            float4 wv = w1r[k];
            wv.x *= sm_; wv.y *= sm_; wv.z *= sm_; wv.w *= sm_;
            dst[k] = wv;
        }
    }
    // (first stage __syncthreads orders sB before GEMM reads)

    float wacc[16];
    #pragma unroll
    for (int k = 0; k < 16; k++) wacc[k] = 0.f;

    const int tx = t & 7;       // GEMM col group (0..7): cols {4tx..} and {32+4tx..}
    const int ty = t >> 3;      // GEMM row base (0..31): rows ty + 32a
    const int rr = t & 63;      // consume/stage row index
    const int pp = t >> 6;      // consume l-part / stage block index

    const float* bcol0 = sB + 4*tx;        // B column base (low half)
    const float* arow0 = buf + ty*PAD_A;   // A row base

    // ============ group loop: 4 bb blocks per iteration ============
    for (int g = 0; g < 16; ++g) {
        const int bb0 = g * 4;

        // ---- stage 4 Wsym blocks into buf-as-A; fuse g-column dot with h ----
        {
            const int u = pp, r = rr;
            const int bb = bb0 + u;
            const float4* p1 = (const float4*)(W2 + (bb*64 + r)*64);
            const float4* p2 = (const float4*)(W2 + (r*64 + bb)*64);
            float* dst = buf + (u*64 + r)*PAD_A;
            float gp = 0.f;
            #pragma unroll
            for (int k = 0; k < 16; ++k) {
                float4 a1 = p1[k];
                float4 a2 = p2[k];
                a1.x += a2.x; a1.y += a2.y; a1.z += a2.z; a1.w += a2.w;
                *(float4*)(dst + 4*k) = a1;
                const float* hp = sh + 4*k;
                gp += a1.x*hp[0] + a1.y*hp[1] + a1.z*hp[2] + a1.w*hp[3];
            }
            sG[r*PAD_G + bb] = gp + b2g[bb*64 + r] + b2g[r*64 + bb];
        }
        __syncthreads();

        // ---- GEMM: Cstack(256x64) = Astack(256x64) @ B(64x64), 8x8 tile/thread
        //      K-chunk of 2 keeps live regs under the 128 cap (no spill) ----
        unsigned long long acc[8][4];
        #pragma unroll
        for (int a = 0; a < 8; ++a) {
            acc[a][0] = 0ull; acc[a][1] = 0ull; acc[a][2] = 0ull; acc[a][3] = 0ull;
        }

        #pragma unroll 1
        for (int m2 = 0; m2 < 64; m2 += 2) {
            unsigned long long bfr[2][4];
            #pragma unroll
            for (int mm = 0; mm < 2; ++mm) {
                const float* brow = bcol0 + (m2 + mm)*PAD_A;
                const float4 bl = *(const float4*)(brow);
                const float4 bh = *(const float4*)(brow + 32);
                bfr[mm][0] = pk2(bl.x, bl.y);
                bfr[mm][1] = pk2(bl.z, bl.w);
                bfr[mm][2] = pk2(bh.x, bh.y);
                bfr[mm][3] = pk2(bh.z, bh.w);
            }
            #pragma unroll
            for (int a = 0; a < 8; ++a) {
                const float2 av = *(const float2*)(arow0 + (32*a)*PAD_A + m2);
                const unsigned long long a0 = pk2(av.x, av.x);
                fma2(acc[a][0], a0, bfr[0][0]);
                fma2(acc[a][1], a0, bfr[0][1]);
                fma2(acc[a][2], a0, bfr[0][2]);
                fma2(acc[a][3], a0, bfr[0][3]);
                const unsigned long long a1 = pk2(av.y, av.y);
                fma2(acc[a][0], a1, bfr[1][0]);
                fma2(acc[a][1], a1, bfr[1][1]);
                fma2(acc[a][2], a1, bfr[1][2]);
                fma2(acc[a][3], a1, bfr[1][3]);
            }
        }
        __syncthreads();   // everyone done reading buf-as-A

        // ---- store C into buf-as-C (pad 65, scalar stores: phase-conflict-free) ----
        #pragma unroll
        for (int a = 0; a < 8; ++a) {
            float* crow = buf + (ty + 32*a)*PAD_C;
            float f0, f1;
            upk2(acc[a][0], f0, f1); crow[4*tx]      = f0; crow[4*tx + 1]      = f1;
            upk2(acc[a][1], f0, f1); crow[4*tx + 2]  = f0; crow[4*tx + 3]      = f1;
            upk2(acc[a][2], f0, f1); crow[32 + 4*tx] = f0; crow[32 + 4*tx + 1] = f1;
            upk2(acc[a][3], f0, f1); crow[32 + 4*tx + 2] = f0; crow[32 + 4*tx + 3] = f1;
        }
        __syncthreads();

        // ---- consume: w[l] += v_bb v_j C[j][l]^2 C[l][j] for the 4 blocks ----
        #pragma unroll
        for (int u = 0; u < 4; ++u) {
            const float coef = sv[bb0 + u] * sv[rr];
            const float* crow  = buf + (u*64 + rr)*PAD_C;
            const float* cbase = buf + (u*64)*PAD_C + rr;
            #pragma unroll
            for (int k = 0; k < 16; ++k) {
                const int l = pp*16 + k;
                const float c  = crow[l];
                const float ct = cbase[l*PAD_C];
                wacc[k] += coef * c * c * ct;
            }
        }
        __syncthreads();   // before next stage overwrites buf
    }

    // ---- reduce wacc over j into rhs column of sG (reuse buf as scratch) ----
    #pragma unroll
    for (int k = 0; k < 16; k++) buf[rr*PAD_C + pp*16 + k] = wacc[k];
    __syncthreads();
    if (t < 64) {
        float s = 0.f;
        for (int r = 0; r < 64; r++) s += buf[r*PAD_C + t];
        sG[t*PAD_G + 64] = s;
    }
    __syncthreads();

    // ---- Gauss-Jordan solve g y = w  (g SPD-ish, no pivoting) ----
    {
        const int r    = t & 63;
        const int part = t >> 6;
        const int cbeg = part * 16;
        for (int p = 0; p < 64; p++) {
            if (t < 64) {
                const float piv = sG[p*PAD_G + p];
                sf[t] = (t == p) ? 0.f : sG[t*PAD_G + p] / piv;
            }
            __syncthreads();
            if (r != p) {
                const float fr = sf[r];
                const float* prow = sG + p*PAD_G;
                float* rrow = sG + r*PAD_G;
                #pragma unroll
                for (int c = 0; c < 16; c++)
                    rrow[cbeg + c] -= fr * prow[cbeg + c];
                if (part == 3)
                    rrow[64] -= fr * prow[64];
            }
            __syncthreads();
        }
    }

    // ---- dv = 0.5 * y ; z = concat(v, dv) ----
    if (t < 64) {
        const float y = sG[t*PAD_G + 64] / sG[t*PAD_G + t];
        sz[t]      = sv[t];
        sz[64 + t] = 0.5f * y;
    }
    __syncthreads();

    // ---- out[n,k] = sum_c z[c] * W3[k, c] ----
    {
        const int k = t >> 2, q = t & 3;
        const float4* w3r = (const float4*)(W3 + k*128 + q*32);
        float p = 0.f;
        #pragma unroll
        for (int j = 0; j < 8; j++) {
            float4 wv = w3r[j];
            const float* zz = sz + q*32 + j*4;
            p += wv.x*zz[0] + wv.y*zz[1] + wv.z*zz[2] + wv.w*zz[3];
        }
        p += __shfl_xor_sync(0xffffffffu, p, 1);
        p += __shfl_xor_sync(0xffffffffu, p, 2);
        if (q == 0) out[n*64 + k] = p;
    }
}

extern "C" void kernel_launch(void* const* d_in, const int* in_sizes, int n_in,
                              void* d_out, int out_size)
{
    // inputs: 0:t (unused), 1:x (256*64), 2:v, 3:W1, 4:b1, 5:W2 (4096*64),
    //         6:b2 (4096), 7:W3 (64*128); output: (256,64) fp32
    const float* x  = (const float*)d_in[1];
    const float* v  = (const float*)d_in[2];
    const float* W1 = (const float*)d_in[3];
    const float* b1 = (const float*)d_in[4];
    const float* W2 = (const float*)d_in[5];
    const float* b2 = (const float*)d_in[6];
    const float* W3 = (const float*)d_in[7];

    cudaFuncSetAttribute(conn_kernel,
                         cudaFuncAttributeMaxDynamicSharedMemorySize, SMEM_BYTES);
    conn_kernel<<<256, TPB, SMEM_BYTES>>>(x, v, W1, b1, W2, b2, W3, (float*)d_out);
}